// round 16
// baseline (speedup 1.0000x reference)
#include <cuda_runtime.h>
#include <cuda_fp16.h>
#include <math.h>
#include <cstdint>

#define Bn 4
#define Cn 64
#define Hn 96
#define Wn 256
#define Mn 4
#define HW (Hn*Wn)
#define NPIX (Bn*Hn*Wn)
#define NELEM (NPIX*Cn)

typedef unsigned long long ull;

// ---------------- mma helpers ----------------------------------------------
__device__ __forceinline__ uint32_t smem_u32(const void* p) {
    uint32_t a;
    asm("{ .reg .u64 t; cvta.to.shared.u64 t, %1; cvt.u32.u64 %0, t; }" : "=r"(a) : "l"(p));
    return a;
}
#define LDSM4(r, addr) \
    asm volatile("ldmatrix.sync.aligned.m8n8.x4.shared.b16 {%0,%1,%2,%3}, [%4];" \
        : "=r"((r)[0]), "=r"((r)[1]), "=r"((r)[2]), "=r"((r)[3]) : "r"(addr))
#define LDSM4T(r, addr) \
    asm volatile("ldmatrix.sync.aligned.m8n8.x4.trans.shared.b16 {%0,%1,%2,%3}, [%4];" \
        : "=r"((r)[0]), "=r"((r)[1]), "=r"((r)[2]), "=r"((r)[3]) : "r"(addr))
#define MMA_F16(ac, a, b0_, b1_) \
    asm volatile("mma.sync.aligned.m16n8k16.row.col.f32.f16.f16.f32 " \
        "{%0,%1,%2,%3},{%4,%5,%6,%7},{%8,%9},{%0,%1,%2,%3};" \
        : "+f"((ac)[0]), "+f"((ac)[1]), "+f"((ac)[2]), "+f"((ac)[3]) \
        : "r"((a)[0]), "r"((a)[1]), "r"((a)[2]), "r"((a)[3]), "r"(b0_), "r"(b1_))
#define MMA_F16ACC(ac, a, b0_, b1_) \
    asm volatile("mma.sync.aligned.m16n8k16.row.col.f16.f16.f16.f16 " \
        "{%0,%1},{%2,%3,%4,%5},{%6,%7},{%0,%1};" \
        : "+r"((ac)[0]), "+r"((ac)[1]) \
        : "r"((a)[0]), "r"((a)[1]), "r"((a)[2]), "r"((a)[3]), "r"(b0_), "r"(b1_))
__device__ __forceinline__ uint32_t exp2pair(float hi, float lo) {
    uint32_t h, r;
    asm("cvt.rn.f16x2.f32 %0, %1, %2;" : "=r"(h) : "f"(hi), "f"(lo));
    asm("ex2.approx.f16x2 %0, %1;" : "=r"(r) : "r"(h));
    return r;
}

// ---------------- scratch (device globals) ---------------------------------
__device__ half g_lnx[2][NELEM];
__device__ half g_w2h[2*4*9*4096];
__device__ half g_Dh[2][Mn*NELEM];
__device__ half g_VT[2][NELEM];
__device__ float g_Z[2][Bn*Cn];
__device__ float g_Sw[2][Bn*Mn*Cn];

// ---------------- fused LN + V projection + (wtrans plane) -----------------
__global__ void __launch_bounds__(256) lnv_kernel(
        const float* __restrict__ x_l, const float* __restrict__ x_r,
        const float* __restrict__ lg, const float* __restrict__ lb,
        const float* __restrict__ rg, const float* __restrict__ rb,
        const float* __restrict__ lw2, const float* __restrict__ lb2,
        const float* __restrict__ rw2, const float* __restrict__ rb2,
        const float* __restrict__ ldw, const float* __restrict__ rdw) {
    int zz = blockIdx.z;
    int t = threadIdx.x;
    if (zz == 8) {
        // weight transform + Z zeroing plane (384 blocks x 256 threads)
        int bid = blockIdx.y*4 + blockIdx.x;
        int gid = bid*256 + t;
        if (gid < 2*Bn*Cn) (&g_Z[0][0])[gid] = 0.f;
        const int n = Mn*9*Cn*Cn;
        for (int i2 = gid; i2 < 2*n; i2 += 384*256) {
            int side = i2 / n, i = i2 % n;
            const float* src = side ? rdw : ldw;
            int ci = i & 63; int r = i >> 6;
            int co = r & 63; r >>= 6;
            int tap = r % 9; int m = r / 9;
            int ky = tap / 3, kx = tap % 3;
            float wv = src[((((m*Cn + co)*Cn + ci)*3 + ky)*3 + kx)];
            g_w2h[(size_t)(((side*4 + m)*9 + tap))*4096 + co*64 + ci] = __float2half(wv);
        }
        return;
    }
    __shared__ float xs[64*68];
    __shared__ half  xh[64*72];
    __shared__ half  wsh[64*72];
    __shared__ half  vs[64*72];
    __shared__ float part[2*256];
    __shared__ float mu_s[64], rs_s[64];
    int w0 = blockIdx.x*64, h = blockIdx.y;
    int side = zz >> 2, b = zz & 3;
    const float* x   = side ? x_r : x_l;
    const float* g   = side ? rg  : lg;
    const float* bia = side ? rb  : lb;
    const float* w2  = side ? rw2 : lw2;
    const float* b2  = side ? rb2 : lb2;
    int lane = t & 31, warp = t >> 5;
    const float* xp = x + (size_t)b*Cn*HW + (size_t)h*Wn + w0;
    #pragma unroll
    for (int k = 0; k < 16; k++) {
        int lin = t + 256*k; int ci = lin >> 6, p = lin & 63;
        xs[ci*68 + p] = xp[(size_t)ci*HW + p];
    }
    #pragma unroll
    for (int k = 0; k < 16; k++) {
        int lin = t + 256*k; int co = lin >> 6, ci = lin & 63;
        wsh[co*72 + ci] = __float2half(w2[co*64 + ci]);
    }
    __syncthreads();
    {
        int q = t >> 6, p = t & 63;
        float s = 0.f, s2 = 0.f;
        #pragma unroll
        for (int i = 0; i < 16; i++) {
            float v = xs[(q*16 + i)*68 + p];
            s += v; s2 += v*v;
        }
        part[q*64 + p] = s;
        part[256 + q*64 + p] = s2;
    }
    __syncthreads();
    if (t < 64) {
        float s  = part[t] + part[64+t] + part[128+t] + part[192+t];
        float s2 = part[256+t] + part[256+64+t] + part[256+128+t] + part[256+192+t];
        float mu = s * (1.f/64.f);
        float var = s2 * (1.f/64.f) - mu*mu;
        mu_s[t] = mu; rs_s[t] = rsqrtf(var + 1e-6f);
    }
    __syncthreads();
    half* op = g_lnx[side] + ((size_t)((b*Hn + h)*Wn + w0))*64;
    #pragma unroll
    for (int k = 0; k < 16; k++) {
        int lin = t + 256*k; int p = lin >> 6, c = lin & 63;
        float xv = xs[c*68 + p];
        float v = (xv - mu_s[p]) * rs_s[p] * g[c] + bia[c];
        op[p*64 + c] = __float2half(v);
        xh[p*72 + c] = __float2half(xv);
    }
    __syncthreads();
    {
        uint32_t xh_u = smem_u32(xh), ws_u = smem_u32(wsh);
        int a_r  = ((lane >> 3) & 1)*8 + (lane & 7);
        int a_kh = lane >> 4;
        int b_n  = (lane >> 4)*8 + (lane & 7);
        int b_kh = (lane >> 3) & 1;
        int pxbase = (warp & 3)*16, cohalf = (warp >> 2)*32;
        float acc[4][4];
        #pragma unroll
        for (int i = 0; i < 4; i++) { acc[i][0]=acc[i][1]=acc[i][2]=acc[i][3]=0.f; }
        #pragma unroll
        for (int ch = 0; ch < 4; ch++) {
            uint32_t af[4], bf[8];
            LDSM4(af, xh_u + (uint32_t)(((pxbase + a_r)*72 + ch*16 + a_kh*8)*2));
            #pragma unroll
            for (int g2 = 0; g2 < 2; g2++)
                LDSM4(bf + g2*4, ws_u + (uint32_t)(((cohalf + g2*16 + b_n)*72 + ch*16 + b_kh*8)*2));
            #pragma unroll
            for (int gg = 0; gg < 4; gg++)
                MMA_F16(acc[gg], af, bf[2*gg], bf[2*gg+1]);
        }
        int r = lane >> 2, c2l = (lane & 3)*2;
        #pragma unroll
        for (int gg = 0; gg < 4; gg++) {
            int co = cohalf + gg*8 + c2l;
            float b0 = b2[co], b1 = b2[co+1];
            vs[co*72 + pxbase + r]           = __float2half(acc[gg][0] + b0);
            vs[(co+1)*72 + pxbase + r]       = __float2half(acc[gg][1] + b1);
            vs[co*72 + pxbase + r + 8]       = __float2half(acc[gg][2] + b0);
            vs[(co+1)*72 + pxbase + r + 8]   = __float2half(acc[gg][3] + b1);
        }
    }
    __syncthreads();
    half* VT = g_VT[side] + (size_t)(b*Hn + h)*64*Wn;
    for (int lin = t; lin < 512; lin += 256) {
        int row = lin >> 3, seg = lin & 7;
        uint4 v = *(const uint4*)&vs[row*72 + seg*8];
        *(uint4*)&VT[row*Wn + w0 + seg*8] = v;
    }
}

// ---------------- dilated conv: full-row CTA, fp16-acc (R13 proven) --------
#define STRIP_S 72
#define WT_S 72
#define S_MAX 272
#define CSM_STRIP 0
#define CSM_WTS  (S_MAX*STRIP_S*2)
#define CSM_ZRED (CSM_WTS + 3*64*WT_S*2)
#define SMEM_CONV (CSM_ZRED + 256)
__global__ void __launch_bounds__(128) conv_mma_kernel(
        const float* __restrict__ ldb, const float* __restrict__ rdb) {
    extern __shared__ char csm[];
    half* strip = (half*)(csm + CSM_STRIP);
    half* wts   = (half*)(csm + CSM_WTS);
    float* zred = (float*)(csm + CSM_ZRED);
    int t = threadIdx.x, lane = t & 31, warp = t >> 5;
    int h = blockIdx.x;
    int zz = blockIdx.y; int side = zz >> 4;
    int bm = zz & 15; int m = bm & 3, b = bm >> 2;
    const float* db = side ? rdb : ldb;
    int d = 2*(m+1), S = 256 + 2*d;
    if (t < 64) zred[t] = 0.f;

    uint32_t acc[4][8][2];
    #pragma unroll
    for (int mt = 0; mt < 4; mt++)
        #pragma unroll
        for (int nt = 0; nt < 8; nt++) { acc[mt][nt][0] = 0u; acc[mt][nt][1] = 0u; }

    uint32_t strip_u = smem_u32(strip);
    uint32_t wts_u   = smem_u32(wts);
    int a_r  = ((lane >> 3) & 1)*8 + (lane & 7);
    int a_kh = lane >> 4;
    int b_n  = (lane >> 4)*8 + (lane & 7);
    int b_kh = (lane >> 3) & 1;

    const half* lnx = g_lnx[side];

    for (int ky = 0; ky < 3; ky++) {
        int hy = h + (ky-1)*d;
        if ((unsigned)hy >= (unsigned)Hn) continue;
        __syncthreads();
        size_t rb = ((size_t)(b*Hn + hy)*Wn)*64;
        for (int lin = t; lin < S*8; lin += 128) {
            int row = lin >> 3, cg = lin & 7;
            int px = row - d;
            uint4 v = make_uint4(0u,0u,0u,0u);
            if ((unsigned)px < (unsigned)Wn)
                v = *(const uint4*)(lnx + rb + (size_t)px*64 + cg*8);
            *(uint4*)&strip[row*STRIP_S + cg*8] = v;
        }
        const half* wsrc = g_w2h + (size_t)((side*4 + m)*9 + ky*3)*4096;
        for (int lin = t; lin < 1536; lin += 128) {
            int tile = lin >> 9, rem = lin & 511;
            int row = rem >> 3, cg = rem & 7;
            uint4 v = *(const uint4*)(wsrc + (size_t)tile*4096 + row*64 + cg*8);
            *(uint4*)&wts[tile*64*WT_S + row*WT_S + cg*8] = v;
        }
        __syncthreads();
        for (int kx = 0; kx < 3; kx++) {
            int rowbase = warp*64 + kx*d;
            uint32_t aA = strip_u + (uint32_t)(((rowbase + a_r)*STRIP_S + a_kh*8)*2);
            uint32_t wB = wts_u + (uint32_t)(((kx*64 + b_n)*WT_S + b_kh*8)*2);
            #pragma unroll
            for (int ch = 0; ch < 4; ch++) {
                uint32_t af[4][4], bf[16];
                #pragma unroll
                for (int g2 = 0; g2 < 4; g2++)
                    LDSM4(bf + g2*4, wB + g2*16*WT_S*2 + ch*32);
                #pragma unroll
                for (int mt = 0; mt < 4; mt++)
                    LDSM4(af[mt], aA + (uint32_t)(mt*16*STRIP_S*2) + ch*32);
                #pragma unroll
                for (int mt = 0; mt < 4; mt++)
                    #pragma unroll
                    for (int nt = 0; nt < 8; nt++)
                        MMA_F16ACC(acc[mt][nt], af[mt], bf[2*nt], bf[2*nt+1]);
            }
        }
    }
    int r = lane >> 2, c2 = (lane & 3)*2;
    half* Dp = g_Dh[side] + (size_t)m*NELEM + ((size_t)((b*Hn + h)*Wn))*64;
    #pragma unroll
    for (int mt = 0; mt < 4; mt++) {
        int px0 = warp*64 + mt*16 + r;
        #pragma unroll
        for (int nt = 0; nt < 8; nt++) {
            int c = nt*8 + c2;
            float b0 = db[m*64 + c], b1 = db[m*64 + c + 1];
            float2 f0 = __half22float2(*(half2*)&acc[mt][nt][0]);
            float2 f1 = __half22float2(*(half2*)&acc[mt][nt][1]);
            float v00 = f0.x + b0, v01 = f0.y + b1;
            float v10 = f1.x + b0, v11 = f1.y + b1;
            *(half2*)&Dp[(size_t)px0*64 + c]     = __floats2half2_rn(v00, v01);
            *(half2*)&Dp[(size_t)(px0+8)*64 + c] = __floats2half2_rn(v10, v11);
            float s0 = v00 + v10, s1 = v01 + v11;
            #pragma unroll
            for (int o = 4; o < 32; o <<= 1) {
                s0 += __shfl_xor_sync(0xffffffffu, s0, o);
                s1 += __shfl_xor_sync(0xffffffffu, s1, o);
            }
            if (lane < 4 && lane == (c2 >> 1)) {
                atomicAdd(&zred[c], s0);
                atomicAdd(&zred[c+1], s1);
            }
        }
    }
    __syncthreads();
    if (t < 64) atomicAdd(&g_Z[side][b*64 + t], zred[t]);
}

// ---------------- SKM gating: smem-staged GEMVs ----------------------------
__global__ void sw_kernel(const float* __restrict__ lc1w, const float* __restrict__ lc1b,
                          const float* __restrict__ lpw,
                          const float* __restrict__ rc1w, const float* __restrict__ rc1b,
                          const float* __restrict__ rpw) {
    __shared__ float Zn[64], Sv[128], lg[256], eb[256], mx[4], sm[4];
    __shared__ float buf[32*256];   // 32KB staging
    int b = blockIdx.x, side = blockIdx.y, t = threadIdx.x;
    const float* c1w = side ? rc1w : lc1w;
    const float* c1b = side ? rc1b : lc1b;
    const float* pw  = side ? rpw  : lpw;
    if (t < 64) Zn[t] = g_Z[side][b*64 + t] * (1.f/(float)HW);
    // stage c1w (8192 floats) coalesced
    for (int lin = t; lin < 8192; lin += 256) buf[lin] = c1w[lin];
    __syncthreads();
    if (t < 128) {
        float s = c1b[t];
        #pragma unroll 8
        for (int c = 0; c < 64; c++) s += Zn[c]*buf[t*64 + c];
        Sv[t] = fmaxf(s, 0.f);
    }
    // pw GEMV in 4 chunks of 32 rows, staged coalesced
    float lgacc = 0.f;
    #pragma unroll
    for (int jc = 0; jc < 4; jc++) {
        __syncthreads();
        const float* pwc = pw + jc*32*256;
        for (int lin = t; lin < 8192; lin += 256) buf[lin] = pwc[lin];
        __syncthreads();
        #pragma unroll 8
        for (int j = 0; j < 32; j++) lgacc += Sv[jc*32 + j]*buf[j*256 + t];
    }
    lg[t] = lgacc;
    __syncthreads();
    if (t < 4) {
        float mm = -1e30f;
        for (int i = 0; i < 64; i++) mm = fmaxf(mm, lg[t*64 + i]);
        mx[t] = mm;
    }
    __syncthreads();
    eb[t] = __expf(lg[t] - mx[t >> 6]);
    __syncthreads();
    if (t < 4) {
        float s = 0.f;
        for (int i = 0; i < 64; i++) s += eb[t*64 + i];
        sm[t] = s;
    }
    __syncthreads();
    g_Sw[side][b*256 + t] = eb[t] / sm[t >> 6];
}

// ---------------- fused cross attention (combine folded in) ----------------
#define EST 264
#define ASMEM (256*EST*2 + 2*256*72*2 + 7168)
__global__ void __launch_bounds__(256, 1) attn_kernel(
        const float* __restrict__ x_l, const float* __restrict__ x_r,
        const float* __restrict__ beta, const float* __restrict__ gamma,
        float* __restrict__ out_l, float* __restrict__ out_r) {
    extern __shared__ char smx[];
    half* E  = (half*)smx;
    half* Qa = E + 256*EST;
    half* Qb = Qa + 256*72;
    half* VTr = Qa;
    half* VTl = Qa + 64*EST;
    float* rowsum = (float*)(smx + 256*EST*2 + 2*256*72*2);
    float* colsum = rowsum + 256;
    float* rowmax = colsum + 256;
    float* alpha  = rowmax + 256;
    float* red    = alpha + 256;
    float* swsl   = red + 64;
    float* swsr   = swsl + 256;
    int bh = blockIdx.x;
    int b = bh / Hn, h = bh % Hn;
    int t = threadIdx.x, lane = t & 31, warp = t >> 5;
    uint32_t Eu = smem_u32(E), Qau = smem_u32(Qa), Qbu = smem_u32(Qb);
    uint32_t VTru = smem_u32(VTr), VTlu = smem_u32(VTl);

    int a_r  = ((lane >> 3) & 1)*8 + (lane & 7);
    int a_kh = lane >> 4;
    int b_n  = (lane >> 4)*8 + (lane & 7);
    int b_kh = (lane >> 3) & 1;
    int e_r  = (lane & 7) + (lane >> 4)*8;
    int e_kh = (lane >> 3) & 1;

    if (t < 256) {
        swsl[t] = g_Sw[0][b*256 + t];
        swsr[t] = g_Sw[1][b*256 + t];
    }
    __syncthreads();
    {
        const half* D0 = g_Dh[0];
        const half* D1 = g_Dh[1];
        size_t dbase = ((size_t)((b*Hn + h)*Wn))*64;
        for (int lin = t; lin < 2048; lin += 256) {
            int row = lin >> 3, cg = lin & 7;
            size_t off = dbase + (size_t)row*64 + cg*8;
            float a[8] = {0,0,0,0,0,0,0,0};
            float bb[8] = {0,0,0,0,0,0,0,0};
            #pragma unroll
            for (int m = 0; m < 4; m++) {
                uint4 v0 = *(const uint4*)(D0 + (size_t)m*NELEM + off);
                uint4 v1 = *(const uint4*)(D1 + (size_t)m*NELEM + off);
                const float* s0 = &swsl[m*64 + cg*8];
                const float* s1 = &swsr[m*64 + cg*8];
                const half2* h0 = (const half2*)&v0;
                const half2* h1 = (const half2*)&v1;
                #pragma unroll
                for (int i = 0; i < 4; i++) {
                    float2 f0 = __half22float2(h0[i]);
                    float2 f1 = __half22float2(h1[i]);
                    a[2*i]   += f0.x * s0[2*i];
                    a[2*i+1] += f0.y * s0[2*i+1];
                    bb[2*i]   += f1.x * s1[2*i];
                    bb[2*i+1] += f1.y * s1[2*i+1];
                }
            }
            half2* qa = (half2*)&Qa[row*72 + cg*8];
            half2* qb = (half2*)&Qb[row*72 + cg*8];
            #pragma unroll
            for (int i = 0; i < 4; i++) {
                qa[i] = __floats2half2_rn(a[2*i], a[2*i+1]);
                qb[i] = __floats2half2_rn(bb[2*i], bb[2*i+1]);
            }
        }
    }
    __syncthreads();

    const float K = 0.125f * 1.44269504f;
    int r = lane >> 2, c2l = (lane & 3)*2;
    for (int pass = 0; pass < 2; pass++) {
        int wbase = pass*128 + warp*16;
        float acc[32][4];
        #pragma unroll
        for (int i = 0; i < 32; i++) { acc[i][0]=acc[i][1]=acc[i][2]=acc[i][3]=0.f; }
        #pragma unroll
        for (int k = 0; k < 4; k++) {
            uint32_t af[4];
            LDSM4(af, Qau + (uint32_t)(((wbase + a_r)*72 + k*16 + a_kh*8)*2));
            #pragma unroll
            for (int g2 = 0; g2 < 16; g2++) {
                uint32_t bf[4];
                LDSM4(bf, Qbu + (uint32_t)(((g2*16 + b_n)*72 + k*16 + b_kh*8)*2));
                MMA_F16(acc[2*g2],   af, bf[0], bf[1]);
                MMA_F16(acc[2*g2+1], af, bf[2], bf[3]);
            }
        }
        float m0 = -1e30f, m1 = -1e30f;
        #pragma unroll
        for (int ti = 0; ti < 32; ti++) {
            m0 = fmaxf(m0, fmaxf(acc[ti][0], acc[ti][1]));
            m1 = fmaxf(m1, fmaxf(acc[ti][2], acc[ti][3]));
        }
        m0 = fmaxf(m0, __shfl_xor_sync(0xffffffffu, m0, 1));
        m0 = fmaxf(m0, __shfl_xor_sync(0xffffffffu, m0, 2));
        m1 = fmaxf(m1, __shfl_xor_sync(0xffffffffu, m1, 1));
        m1 = fmaxf(m1, __shfl_xor_sync(0xffffffffu, m1, 2));
        float rs0 = 0.f, rs1 = 0.f;
        #pragma unroll
        for (int ti = 0; ti < 32; ti++) {
            int v = ti*8 + c2l;
            uint32_t e0 = exp2pair((acc[ti][1]-m0)*K, (acc[ti][0]-m0)*K);
            uint32_t e1 = exp2pair((acc[ti][3]-m1)*K, (acc[ti][2]-m1)*K);
            *(uint32_t*)&E[(wbase+r)*EST + v]   = e0;
            *(uint32_t*)&E[(wbase+r+8)*EST + v] = e1;
            float2 f0 = __half22float2(*(half2*)&e0);
            float2 f1 = __half22float2(*(half2*)&e1);
            rs0 += f0.x + f0.y;
            rs1 += f1.x + f1.y;
        }
        rs0 += __shfl_xor_sync(0xffffffffu, rs0, 1);
        rs0 += __shfl_xor_sync(0xffffffffu, rs0, 2);
        rs1 += __shfl_xor_sync(0xffffffffu, rs1, 1);
        rs1 += __shfl_xor_sync(0xffffffffu, rs1, 2);
        if ((lane & 3) == 0) {
            rowsum[wbase+r] = rs0;   rowmax[wbase+r] = m0;
            rowsum[wbase+r+8] = rs1; rowmax[wbase+r+8] = m1;
        }
    }
    __syncthreads();
    if (warp == 0) {
        float gm = -1e30f;
        #pragma unroll
        for (int i = 0; i < 8; i++) gm = fmaxf(gm, rowmax[lane + i*32]);
        #pragma unroll
        for (int o = 16; o > 0; o >>= 1) gm = fmaxf(gm, __shfl_xor_sync(0xffffffffu, gm, o));
        if (lane == 0) red[0] = gm;
    }
    __syncthreads();
    alpha[t] = exp2f((rowmax[t] - red[0]) * K);
    __syncthreads();
    {
        float cs = 0.f;
        #pragma unroll 8
        for (int rr = 0; rr < 256; rr++) cs += __half2float(E[rr*EST + t]) * alpha[rr];
        colsum[t] = cs;
    }
    const half* Vlp = g_VT[0] + (size_t)bh*64*Wn;
    const half* Vrp = g_VT[1] + (size_t)bh*64*Wn;
    for (int lin = t; lin < 2048; lin += 256) {
        int row = lin >> 5, seg = lin & 31;
        *(uint4*)&VTr[row*EST + seg*8] = *(const uint4*)(Vrp + row*Wn + seg*8);
        uint4 v = *(const uint4*)(Vlp + row*Wn + seg*8);
        half2* hp = (half2*)&v;
        #pragma unroll
        for (int i = 0; i < 4; i++) {
            float2 f = __half22float2(hp[i]);
            f.x *= alpha[seg*8 + 2*i];
            f.y *= alpha[seg*8 + 2*i + 1];
            hp[i] = __floats2half2_rn(f.x, f.y);
        }
        *(uint4*)&VTl[row*EST + seg*8] = v;
    }
    __syncthreads();

    for (int pass = 0; pass < 2; pass++) {
        int wbase = pass*128 + warp*16;
        float acc[8][4];
        #pragma unroll
        for (int i = 0; i < 8; i++) { acc[i][0]=acc[i][1]=acc[i][2]=acc[i][3]=0.f; }
        #pragma unroll 4
        for (int k = 0; k < 16; k++) {
            uint32_t af[4];
            LDSM4(af, Eu + (uint32_t)(((wbase + a_r)*EST + k*16 + a_kh*8)*2));
            #pragma unroll
            for (int g2 = 0; g2 < 4; g2++) {
                uint32_t bf[4];
                LDSM4(bf, VTru + (uint32_t)(((g2*16 + b_n)*EST + k*16 + b_kh*8)*2));
                MMA_F16(acc[2*g2],   af, bf[0], bf[1]);
                MMA_F16(acc[2*g2+1], af, bf[2], bf[3]);
            }
        }
        int w0r = wbase + r;
        float inv0 = __frcp_rn(rowsum[w0r]), inv1 = __frcp_rn(rowsum[w0r+8]);
        #pragma unroll
        for (int tile = 0; tile < 8; tile++) {
            int c = tile*8 + c2l;
            float bc0 = __ldg(&beta[c]), bc1 = __ldg(&beta[c+1]);
            size_t i00 = ((size_t)(b*64 + c)*Hn + h)*Wn + w0r;
            out_l[i00]      = x_l[i00]      + bc0*acc[tile][0]*inv0;
            out_l[i00+HW]   = x_l[i00+HW]   + bc1*acc[tile][1]*inv0;
            out_l[i00+8]    = x_l[i00+8]    + bc0*acc[tile][2]*inv1;
            out_l[i00+HW+8] = x_l[i00+HW+8] + bc1*acc[tile][3]*inv1;
        }
    }
    for (int pass = 0; pass < 2; pass++) {
        int vbase = pass*128 + warp*16;
        float acc[8][4];
        #pragma unroll
        for (int i = 0; i < 8; i++) { acc[i][0]=acc[i][1]=acc[i][2]=acc[i][3]=0.f; }
        #pragma unroll 4
        for (int k = 0; k < 16; k++) {
            uint32_t af[4];
            LDSM4T(af, Eu + (uint32_t)(((k*16 + e_r)*EST + vbase + e_kh*8)*2));
            #pragma unroll
            for (int g2 = 0; g2 < 4; g2++) {
                uint32_t bf[4];
                LDSM4(bf, VTlu + (uint32_t)(((g2*16 + b_n)*EST + k*16 + b_kh*8)*2));
                MMA_F16(acc[2*g2],   af, bf[0], bf[1]);
                MMA_F16(acc[2*g2+1], af, bf[2], bf[3]);
            }
        }
        int v0r = vbase + r;
        float inv0 = __frcp_rn(colsum[v0r]), inv1 = __frcp_rn(colsum[v0r+8]);
        #pragma unroll
        for (int tile = 0; tile < 8; tile++) {
            int c = tile*8 + c2l;
            float gc0 = __ldg(&gamma[c]), gc1 = __ldg(&gamma[c+1]);
            size_t i00 = ((size_t)(b*64 + c)*Hn + h)*Wn + v0r;
            out_r[i00]      = x_r[i00]      + gc0*acc[tile][0]*inv0;
            out_r[i00+HW]   = x_r[i00+HW]   + gc1*acc[tile][1]*inv0;
            out_r[i00+8]    = x_r[i00+8]    + gc0*acc[tile][2]*inv1;
            out_r[i00+HW+8] = x_r[i00+HW+8] + gc1*acc[tile][3]*inv1;
        }
    }
}

// ---------------- launch ----------------------------------------------------
extern "C" void kernel_launch(void* const* d_in, const int* in_sizes, int n_in,
                              void* d_out, int out_size) {
    const float* x_l   = (const float*)d_in[0];
    const float* x_r   = (const float*)d_in[1];
    const float* lnl_g = (const float*)d_in[2];
    const float* lnl_b = (const float*)d_in[3];
    const float* lnr_g = (const float*)d_in[4];
    const float* lnr_b = (const float*)d_in[5];
    const float* l_dw  = (const float*)d_in[6];
    const float* l_db  = (const float*)d_in[7];
    const float* l_c1w = (const float*)d_in[8];
    const float* l_c1b = (const float*)d_in[9];
    const float* l_pw  = (const float*)d_in[10];
    const float* r_dw  = (const float*)d_in[11];
    const float* r_db  = (const float*)d_in[12];
    const float* r_c1w = (const float*)d_in[13];
    const float* r_c1b = (const float*)d_in[14];
    const float* r_pw  = (const float*)d_in[15];
    const float* l2w   = (const float*)d_in[16];
    const float* l2b   = (const float*)d_in[17];
    const float* r2w   = (const float*)d_in[18];
    const float* r2b   = (const float*)d_in[19];
    const float* beta  = (const float*)d_in[20];
    const float* gamma = (const float*)d_in[21];
    float* out_l = (float*)d_out;
    float* out_r = out_l + (size_t)NELEM;

    cudaFuncSetAttribute(attn_kernel, cudaFuncAttributeMaxDynamicSharedMemorySize, ASMEM);
    cudaFuncSetAttribute(conv_mma_kernel, cudaFuncAttributeMaxDynamicSharedMemorySize, SMEM_CONV);

    dim3 tgrid(Wn/64, Hn, 2*Bn + 1);
    lnv_kernel<<<tgrid, 256>>>(x_l, x_r, lnl_g, lnl_b, lnr_g, lnr_b,
                               l2w, l2b, r2w, r2b, l_dw, r_dw);        // 1

    dim3 cgrid(Hn, 2*Bn*Mn);
    conv_mma_kernel<<<cgrid, 128, SMEM_CONV>>>(l_db, r_db);            // 2

    dim3 sgrid(Bn, 2);
    sw_kernel<<<sgrid, 256>>>(l_c1w, l_c1b, l_pw, r_c1w, r_c1b, r_pw); // 3

    attn_kernel<<<Bn*Hn, 256, ASMEM>>>(x_l, x_r, beta, gamma, out_l, out_r); // 4 <- ncu
}

// round 17
// speedup vs baseline: 1.0216x; 1.0216x over previous
#include <cuda_runtime.h>
#include <cuda_fp16.h>
#include <math.h>
#include <cstdint>

#define Bn 4
#define Cn 64
#define Hn 96
#define Wn 256
#define Mn 4
#define HW (Hn*Wn)
#define NPIX (Bn*Hn*Wn)
#define NELEM (NPIX*Cn)

typedef unsigned long long ull;

// ---------------- mma helpers ----------------------------------------------
__device__ __forceinline__ uint32_t smem_u32(const void* p) {
    uint32_t a;
    asm("{ .reg .u64 t; cvta.to.shared.u64 t, %1; cvt.u32.u64 %0, t; }" : "=r"(a) : "l"(p));
    return a;
}
#define LDSM4(r, addr) \
    asm volatile("ldmatrix.sync.aligned.m8n8.x4.shared.b16 {%0,%1,%2,%3}, [%4];" \
        : "=r"((r)[0]), "=r"((r)[1]), "=r"((r)[2]), "=r"((r)[3]) : "r"(addr))
#define LDSM4T(r, addr) \
    asm volatile("ldmatrix.sync.aligned.m8n8.x4.trans.shared.b16 {%0,%1,%2,%3}, [%4];" \
        : "=r"((r)[0]), "=r"((r)[1]), "=r"((r)[2]), "=r"((r)[3]) : "r"(addr))
#define MMA_F16(ac, a, b0_, b1_) \
    asm volatile("mma.sync.aligned.m16n8k16.row.col.f32.f16.f16.f32 " \
        "{%0,%1,%2,%3},{%4,%5,%6,%7},{%8,%9},{%0,%1,%2,%3};" \
        : "+f"((ac)[0]), "+f"((ac)[1]), "+f"((ac)[2]), "+f"((ac)[3]) \
        : "r"((a)[0]), "r"((a)[1]), "r"((a)[2]), "r"((a)[3]), "r"(b0_), "r"(b1_))
#define MMA_F16ACC(ac, a, b0_, b1_) \
    asm volatile("mma.sync.aligned.m16n8k16.row.col.f16.f16.f16.f16 " \
        "{%0,%1},{%2,%3,%4,%5},{%6,%7},{%0,%1};" \
        : "+r"((ac)[0]), "+r"((ac)[1]) \
        : "r"((a)[0]), "r"((a)[1]), "r"((a)[2]), "r"((a)[3]), "r"(b0_), "r"(b1_))
__device__ __forceinline__ uint32_t exp2pair(float hi, float lo) {
    uint32_t h, r;
    asm("cvt.rn.f16x2.f32 %0, %1, %2;" : "=r"(h) : "f"(hi), "f"(lo));
    asm("ex2.approx.f16x2 %0, %1;" : "=r"(r) : "r"(h));
    return r;
}

// ---------------- scratch (device globals) ---------------------------------
__device__ half g_lnx[2][NELEM];
__device__ half g_w2h[2*4*9*4096];
__device__ half g_Dh[2][Mn*NELEM];
__device__ half g_VT[2][NELEM];
__device__ float g_Z[2][Bn*Cn];
__device__ float g_Sw[2][Bn*Mn*Cn];

// ---------------- fused LN + V projection + (wtrans plane) -----------------
__global__ void __launch_bounds__(256) lnv_kernel(
        const float* __restrict__ x_l, const float* __restrict__ x_r,
        const float* __restrict__ lg, const float* __restrict__ lb,
        const float* __restrict__ rg, const float* __restrict__ rb,
        const float* __restrict__ lw2, const float* __restrict__ lb2,
        const float* __restrict__ rw2, const float* __restrict__ rb2,
        const float* __restrict__ ldw, const float* __restrict__ rdw) {
    int zz = blockIdx.z;
    int t = threadIdx.x;
    if (zz == 8) {
        int bid = blockIdx.y*4 + blockIdx.x;
        int gid = bid*256 + t;
        if (gid < 2*Bn*Cn) (&g_Z[0][0])[gid] = 0.f;
        const int n = Mn*9*Cn*Cn;
        for (int i2 = gid; i2 < 2*n; i2 += 384*256) {
            int side = i2 / n, i = i2 % n;
            const float* src = side ? rdw : ldw;
            int ci = i & 63; int r = i >> 6;
            int co = r & 63; r >>= 6;
            int tap = r % 9; int m = r / 9;
            int ky = tap / 3, kx = tap % 3;
            float wv = src[((((m*Cn + co)*Cn + ci)*3 + ky)*3 + kx)];
            g_w2h[(size_t)(((side*4 + m)*9 + tap))*4096 + co*64 + ci] = __float2half(wv);
        }
        return;
    }
    __shared__ float xs[64*68];
    __shared__ half  xh[64*72];
    __shared__ half  wsh[64*72];
    __shared__ half  vs[64*72];
    __shared__ float part[2*256];
    __shared__ float mu_s[64], rs_s[64];
    int w0 = blockIdx.x*64, h = blockIdx.y;
    int side = zz >> 2, b = zz & 3;
    const float* x   = side ? x_r : x_l;
    const float* g   = side ? rg  : lg;
    const float* bia = side ? rb  : lb;
    const float* w2  = side ? rw2 : lw2;
    const float* b2  = side ? rb2 : lb2;
    int lane = t & 31, warp = t >> 5;
    const float* xp = x + (size_t)b*Cn*HW + (size_t)h*Wn + w0;
    #pragma unroll
    for (int k = 0; k < 16; k++) {
        int lin = t + 256*k; int ci = lin >> 6, p = lin & 63;
        xs[ci*68 + p] = xp[(size_t)ci*HW + p];
    }
    #pragma unroll
    for (int k = 0; k < 16; k++) {
        int lin = t + 256*k; int co = lin >> 6, ci = lin & 63;
        wsh[co*72 + ci] = __float2half(w2[co*64 + ci]);
    }
    __syncthreads();
    {
        int q = t >> 6, p = t & 63;
        float s = 0.f, s2 = 0.f;
        #pragma unroll
        for (int i = 0; i < 16; i++) {
            float v = xs[(q*16 + i)*68 + p];
            s += v; s2 += v*v;
        }
        part[q*64 + p] = s;
        part[256 + q*64 + p] = s2;
    }
    __syncthreads();
    if (t < 64) {
        float s  = part[t] + part[64+t] + part[128+t] + part[192+t];
        float s2 = part[256+t] + part[256+64+t] + part[256+128+t] + part[256+192+t];
        float mu = s * (1.f/64.f);
        float var = s2 * (1.f/64.f) - mu*mu;
        mu_s[t] = mu; rs_s[t] = rsqrtf(var + 1e-6f);
    }
    __syncthreads();
    half* op = g_lnx[side] + ((size_t)((b*Hn + h)*Wn + w0))*64;
    #pragma unroll
    for (int k = 0; k < 16; k++) {
        int lin = t + 256*k; int p = lin >> 6, c = lin & 63;
        float xv = xs[c*68 + p];
        float v = (xv - mu_s[p]) * rs_s[p] * g[c] + bia[c];
        op[p*64 + c] = __float2half(v);
        xh[p*72 + c] = __float2half(xv);
    }
    __syncthreads();
    {
        uint32_t xh_u = smem_u32(xh), ws_u = smem_u32(wsh);
        int a_r  = ((lane >> 3) & 1)*8 + (lane & 7);
        int a_kh = lane >> 4;
        int b_n  = (lane >> 4)*8 + (lane & 7);
        int b_kh = (lane >> 3) & 1;
        int pxbase = (warp & 3)*16, cohalf = (warp >> 2)*32;
        float acc[4][4];
        #pragma unroll
        for (int i = 0; i < 4; i++) { acc[i][0]=acc[i][1]=acc[i][2]=acc[i][3]=0.f; }
        #pragma unroll
        for (int ch = 0; ch < 4; ch++) {
            uint32_t af[4], bf[8];
            LDSM4(af, xh_u + (uint32_t)(((pxbase + a_r)*72 + ch*16 + a_kh*8)*2));
            #pragma unroll
            for (int g2 = 0; g2 < 2; g2++)
                LDSM4(bf + g2*4, ws_u + (uint32_t)(((cohalf + g2*16 + b_n)*72 + ch*16 + b_kh*8)*2));
            #pragma unroll
            for (int gg = 0; gg < 4; gg++)
                MMA_F16(acc[gg], af, bf[2*gg], bf[2*gg+1]);
        }
        int r = lane >> 2, c2l = (lane & 3)*2;
        #pragma unroll
        for (int gg = 0; gg < 4; gg++) {
            int co = cohalf + gg*8 + c2l;
            float b0 = b2[co], b1 = b2[co+1];
            vs[co*72 + pxbase + r]           = __float2half(acc[gg][0] + b0);
            vs[(co+1)*72 + pxbase + r]       = __float2half(acc[gg][1] + b1);
            vs[co*72 + pxbase + r + 8]       = __float2half(acc[gg][2] + b0);
            vs[(co+1)*72 + pxbase + r + 8]   = __float2half(acc[gg][3] + b1);
        }
    }
    __syncthreads();
    half* VT = g_VT[side] + (size_t)(b*Hn + h)*64*Wn;
    for (int lin = t; lin < 512; lin += 256) {
        int row = lin >> 3, seg = lin & 7;
        uint4 v = *(const uint4*)&vs[row*72 + seg*8];
        *(uint4*)&VT[row*Wn + w0 + seg*8] = v;
    }
}

// ---------------- dilated conv: full-row CTA, fp16-acc (R13 proven) --------
#define STRIP_S 72
#define WT_S 72
#define S_MAX 272
#define CSM_STRIP 0
#define CSM_WTS  (S_MAX*STRIP_S*2)
#define CSM_ZRED (CSM_WTS + 3*64*WT_S*2)
#define SMEM_CONV (CSM_ZRED + 256)
__global__ void __launch_bounds__(128) conv_mma_kernel(
        const float* __restrict__ ldb, const float* __restrict__ rdb) {
    extern __shared__ char csm[];
    half* strip = (half*)(csm + CSM_STRIP);
    half* wts   = (half*)(csm + CSM_WTS);
    float* zred = (float*)(csm + CSM_ZRED);
    int t = threadIdx.x, lane = t & 31, warp = t >> 5;
    int h = blockIdx.x;
    int zz = blockIdx.y; int side = zz >> 4;
    int bm = zz & 15; int m = bm & 3, b = bm >> 2;
    const float* db = side ? rdb : ldb;
    int d = 2*(m+1), S = 256 + 2*d;
    if (t < 64) zred[t] = 0.f;

    uint32_t acc[4][8][2];
    #pragma unroll
    for (int mt = 0; mt < 4; mt++)
        #pragma unroll
        for (int nt = 0; nt < 8; nt++) { acc[mt][nt][0] = 0u; acc[mt][nt][1] = 0u; }

    uint32_t strip_u = smem_u32(strip);
    uint32_t wts_u   = smem_u32(wts);
    int a_r  = ((lane >> 3) & 1)*8 + (lane & 7);
    int a_kh = lane >> 4;
    int b_n  = (lane >> 4)*8 + (lane & 7);
    int b_kh = (lane >> 3) & 1;

    const half* lnx = g_lnx[side];

    for (int ky = 0; ky < 3; ky++) {
        int hy = h + (ky-1)*d;
        if ((unsigned)hy >= (unsigned)Hn) continue;
        __syncthreads();
        size_t rb = ((size_t)(b*Hn + hy)*Wn)*64;
        for (int lin = t; lin < S*8; lin += 128) {
            int row = lin >> 3, cg = lin & 7;
            int px = row - d;
            uint4 v = make_uint4(0u,0u,0u,0u);
            if ((unsigned)px < (unsigned)Wn)
                v = *(const uint4*)(lnx + rb + (size_t)px*64 + cg*8);
            *(uint4*)&strip[row*STRIP_S + cg*8] = v;
        }
        const half* wsrc = g_w2h + (size_t)((side*4 + m)*9 + ky*3)*4096;
        for (int lin = t; lin < 1536; lin += 128) {
            int tile = lin >> 9, rem = lin & 511;
            int row = rem >> 3, cg = rem & 7;
            uint4 v = *(const uint4*)(wsrc + (size_t)tile*4096 + row*64 + cg*8);
            *(uint4*)&wts[tile*64*WT_S + row*WT_S + cg*8] = v;
        }
        __syncthreads();
        for (int kx = 0; kx < 3; kx++) {
            int rowbase = warp*64 + kx*d;
            uint32_t aA = strip_u + (uint32_t)(((rowbase + a_r)*STRIP_S + a_kh*8)*2);
            uint32_t wB = wts_u + (uint32_t)(((kx*64 + b_n)*WT_S + b_kh*8)*2);
            #pragma unroll
            for (int ch = 0; ch < 4; ch++) {
                uint32_t af[4][4], bf[16];
                #pragma unroll
                for (int g2 = 0; g2 < 4; g2++)
                    LDSM4(bf + g2*4, wB + g2*16*WT_S*2 + ch*32);
                #pragma unroll
                for (int mt = 0; mt < 4; mt++)
                    LDSM4(af[mt], aA + (uint32_t)(mt*16*STRIP_S*2) + ch*32);
                #pragma unroll
                for (int mt = 0; mt < 4; mt++)
                    #pragma unroll
                    for (int nt = 0; nt < 8; nt++)
                        MMA_F16ACC(acc[mt][nt], af[mt], bf[2*nt], bf[2*nt+1]);
            }
        }
    }
    int r = lane >> 2, c2 = (lane & 3)*2;
    half* Dp = g_Dh[side] + (size_t)m*NELEM + ((size_t)((b*Hn + h)*Wn))*64;
    #pragma unroll
    for (int mt = 0; mt < 4; mt++) {
        int px0 = warp*64 + mt*16 + r;
        #pragma unroll
        for (int nt = 0; nt < 8; nt++) {
            int c = nt*8 + c2;
            float b0 = db[m*64 + c], b1 = db[m*64 + c + 1];
            float2 f0 = __half22float2(*(half2*)&acc[mt][nt][0]);
            float2 f1 = __half22float2(*(half2*)&acc[mt][nt][1]);
            float v00 = f0.x + b0, v01 = f0.y + b1;
            float v10 = f1.x + b0, v11 = f1.y + b1;
            *(half2*)&Dp[(size_t)px0*64 + c]     = __floats2half2_rn(v00, v01);
            *(half2*)&Dp[(size_t)(px0+8)*64 + c] = __floats2half2_rn(v10, v11);
            float s0 = v00 + v10, s1 = v01 + v11;
            #pragma unroll
            for (int o = 4; o < 32; o <<= 1) {
                s0 += __shfl_xor_sync(0xffffffffu, s0, o);
                s1 += __shfl_xor_sync(0xffffffffu, s1, o);
            }
            if (lane < 4 && lane == (c2 >> 1)) {
                atomicAdd(&zred[c], s0);
                atomicAdd(&zred[c+1], s1);
            }
        }
    }
    __syncthreads();
    if (t < 64) atomicAdd(&g_Z[side][b*64 + t], zred[t]);
}

// ---------------- SKM gating: smem-staged GEMVs ----------------------------
__global__ void sw_kernel(const float* __restrict__ lc1w, const float* __restrict__ lc1b,
                          const float* __restrict__ lpw,
                          const float* __restrict__ rc1w, const float* __restrict__ rc1b,
                          const float* __restrict__ rpw) {
    __shared__ float Zn[64], Sv[128], lg[256], eb[256], mx[4], sm[4];
    __shared__ float buf[32*256];
    int b = blockIdx.x, side = blockIdx.y, t = threadIdx.x;
    const float* c1w = side ? rc1w : lc1w;
    const float* c1b = side ? rc1b : lc1b;
    const float* pw  = side ? rpw  : lpw;
    if (t < 64) Zn[t] = g_Z[side][b*64 + t] * (1.f/(float)HW);
    for (int lin = t; lin < 8192; lin += 256) buf[lin] = c1w[lin];
    __syncthreads();
    if (t < 128) {
        float s = c1b[t];
        #pragma unroll 8
        for (int c = 0; c < 64; c++) s += Zn[c]*buf[t*64 + c];
        Sv[t] = fmaxf(s, 0.f);
    }
    float lgacc = 0.f;
    #pragma unroll
    for (int jc = 0; jc < 4; jc++) {
        __syncthreads();
        const float* pwc = pw + jc*32*256;
        for (int lin = t; lin < 8192; lin += 256) buf[lin] = pwc[lin];
        __syncthreads();
        #pragma unroll 8
        for (int j = 0; j < 32; j++) lgacc += Sv[jc*32 + j]*buf[j*256 + t];
    }
    lg[t] = lgacc;
    __syncthreads();
    if (t < 4) {
        float mm = -1e30f;
        for (int i = 0; i < 64; i++) mm = fmaxf(mm, lg[t*64 + i]);
        mx[t] = mm;
    }
    __syncthreads();
    eb[t] = __expf(lg[t] - mx[t >> 6]);
    __syncthreads();
    if (t < 4) {
        float s = 0.f;
        for (int i = 0; i < 64; i++) s += eb[t*64 + i];
        sm[t] = s;
    }
    __syncthreads();
    g_Sw[side][b*256 + t] = eb[t] / sm[t >> 6];
}

// ---------------- fused cross attention: 512 threads -----------------------
#define EST 264
#define F_CNT 3136
#define ASMEM (256*EST*2 + 2*256*72*2 + F_CNT*4)
__global__ void __launch_bounds__(512, 1) attn_kernel(
        const float* __restrict__ x_l, const float* __restrict__ x_r,
        const float* __restrict__ beta, const float* __restrict__ gamma,
        float* __restrict__ out_l, float* __restrict__ out_r) {
    extern __shared__ char smx[];
    half* E  = (half*)smx;
    half* Qa = E + 256*EST;
    half* Qb = Qa + 256*72;
    half* VTr = Qa;
    half* VTl = Qa + 64*EST;
    float* fb = (float*)(smx + 256*EST*2 + 2*256*72*2);
    float* rowsum = fb;            // 256
    float* colsum = fb + 256;      // 256
    float* rowmax = fb + 512;      // 256
    float* alpha  = fb + 768;      // 256
    float* red    = fb + 1024;     // 64
    float* swsl   = fb + 1088;     // 256
    float* swsr   = fb + 1344;     // 256
    float* pmax   = fb + 1600;     // 512
    float* prsum  = fb + 2112;     // 512
    float* csp    = fb + 2624;     // 512
    int bh = blockIdx.x;
    int b = bh / Hn, h = bh % Hn;
    int t = threadIdx.x, lane = t & 31, warp = t >> 5;   // 16 warps
    uint32_t Eu = smem_u32(E), Qau = smem_u32(Qa), Qbu = smem_u32(Qb);
    uint32_t VTru = smem_u32(VTr), VTlu = smem_u32(VTl);

    int a_r  = ((lane >> 3) & 1)*8 + (lane & 7);
    int a_kh = lane >> 4;
    int b_n  = (lane >> 4)*8 + (lane & 7);
    int b_kh = (lane >> 3) & 1;
    int e_r  = (lane & 7) + (lane >> 4)*8;
    int e_kh = (lane >> 3) & 1;
    int whalf = warp >> 3, wlow = warp & 7;
    int r = lane >> 2, c2l = (lane & 3)*2;

    if (t < 256) swsl[t] = g_Sw[0][b*256 + t];
    else         swsr[t-256] = g_Sw[1][b*256 + t - 256];
    __syncthreads();
    // Q build: Qa/Qb = sum_m Sw * D
    {
        const half* D0 = g_Dh[0];
        const half* D1 = g_Dh[1];
        size_t dbase = ((size_t)((b*Hn + h)*Wn))*64;
        #pragma unroll
        for (int it = 0; it < 4; it++) {
            int lin = t + it*512;
            int row = lin >> 3, cg = lin & 7;
            size_t off = dbase + (size_t)row*64 + cg*8;
            float a[8] = {0,0,0,0,0,0,0,0};
            float bb[8] = {0,0,0,0,0,0,0,0};
            #pragma unroll
            for (int m = 0; m < 4; m++) {
                uint4 v0 = *(const uint4*)(D0 + (size_t)m*NELEM + off);
                uint4 v1 = *(const uint4*)(D1 + (size_t)m*NELEM + off);
                const float* s0 = &swsl[m*64 + cg*8];
                const float* s1 = &swsr[m*64 + cg*8];
                const half2* h0 = (const half2*)&v0;
                const half2* h1 = (const half2*)&v1;
                #pragma unroll
                for (int i = 0; i < 4; i++) {
                    float2 f0 = __half22float2(h0[i]);
                    float2 f1 = __half22float2(h1[i]);
                    a[2*i]   += f0.x * s0[2*i];
                    a[2*i+1] += f0.y * s0[2*i+1];
                    bb[2*i]   += f1.x * s1[2*i];
                    bb[2*i+1] += f1.y * s1[2*i+1];
                }
            }
            half2* qa = (half2*)&Qa[row*72 + cg*8];
            half2* qb = (half2*)&Qb[row*72 + cg*8];
            #pragma unroll
            for (int i = 0; i < 4; i++) {
                qa[i] = __floats2half2_rn(a[2*i], a[2*i+1]);
                qb[i] = __floats2half2_rn(bb[2*i], bb[2*i+1]);
            }
        }
    }
    __syncthreads();

    const float K = 0.125f * 1.44269504f;
    // QK: warp -> 16 rows x 128 cols
    for (int pass = 0; pass < 2; pass++) {
        int wrow = (pass*8 + wlow)*16;
        int wcol = whalf*128;
        float acc[16][4];
        #pragma unroll
        for (int i = 0; i < 16; i++) { acc[i][0]=acc[i][1]=acc[i][2]=acc[i][3]=0.f; }
        #pragma unroll
        for (int k = 0; k < 4; k++) {
            uint32_t af[4];
            LDSM4(af, Qau + (uint32_t)(((wrow + a_r)*72 + k*16 + a_kh*8)*2));
            #pragma unroll
            for (int g2 = 0; g2 < 8; g2++) {
                uint32_t bf[4];
                LDSM4(bf, Qbu + (uint32_t)(((wcol + g2*16 + b_n)*72 + k*16 + b_kh*8)*2));
                MMA_F16(acc[2*g2],   af, bf[0], bf[1]);
                MMA_F16(acc[2*g2+1], af, bf[2], bf[3]);
            }
        }
        float m0 = -1e30f, m1 = -1e30f;
        #pragma unroll
        for (int ti = 0; ti < 16; ti++) {
            m0 = fmaxf(m0, fmaxf(acc[ti][0], acc[ti][1]));
            m1 = fmaxf(m1, fmaxf(acc[ti][2], acc[ti][3]));
        }
        m0 = fmaxf(m0, __shfl_xor_sync(0xffffffffu, m0, 1));
        m0 = fmaxf(m0, __shfl_xor_sync(0xffffffffu, m0, 2));
        m1 = fmaxf(m1, __shfl_xor_sync(0xffffffffu, m1, 1));
        m1 = fmaxf(m1, __shfl_xor_sync(0xffffffffu, m1, 2));
        if ((lane & 3) == 0) {
            pmax[whalf*256 + wrow + r] = m0;
            pmax[whalf*256 + wrow + r + 8] = m1;
        }
        __syncthreads();
        float g0 = fmaxf(pmax[wrow + r],     pmax[256 + wrow + r]);
        float g1 = fmaxf(pmax[wrow + r + 8], pmax[256 + wrow + r + 8]);
        float rs0 = 0.f, rs1 = 0.f;
        #pragma unroll
        for (int ti = 0; ti < 16; ti++) {
            int v = wcol + ti*8 + c2l;
            uint32_t e0 = exp2pair((acc[ti][1]-g0)*K, (acc[ti][0]-g0)*K);
            uint32_t e1 = exp2pair((acc[ti][3]-g1)*K, (acc[ti][2]-g1)*K);
            *(uint32_t*)&E[(wrow+r)*EST + v]   = e0;
            *(uint32_t*)&E[(wrow+r+8)*EST + v] = e1;
            float2 f0 = __half22float2(*(half2*)&e0);
            float2 f1 = __half22float2(*(half2*)&e1);
            rs0 += f0.x + f0.y;
            rs1 += f1.x + f1.y;
        }
        rs0 += __shfl_xor_sync(0xffffffffu, rs0, 1);
        rs0 += __shfl_xor_sync(0xffffffffu, rs0, 2);
        rs1 += __shfl_xor_sync(0xffffffffu, rs1, 1);
        rs1 += __shfl_xor_sync(0xffffffffu, rs1, 2);
        if ((lane & 3) == 0) {
            prsum[whalf*256 + wrow + r] = rs0;
            prsum[whalf*256 + wrow + r + 8] = rs1;
        }
        __syncthreads();
    }
    if (t < 256) {
        rowmax[t] = fmaxf(pmax[t], pmax[256 + t]);
        rowsum[t] = prsum[t] + prsum[256 + t];
    }
    __syncthreads();
    if (warp == 0) {
        float gm = -1e30f;
        #pragma unroll
        for (int i = 0; i < 8; i++) gm = fmaxf(gm, rowmax[lane + i*32]);
        #pragma unroll
        for (int o = 16; o > 0; o >>= 1) gm = fmaxf(gm, __shfl_xor_sync(0xffffffffu, gm, o));
        if (lane == 0) red[0] = gm;
    }
    __syncthreads();
    if (t < 256) alpha[t] = exp2f((rowmax[t] - red[0]) * K);
    __syncthreads();
    // partial colsums (row halves) + VT staging
    {
        int col = t & 255, hf = t >> 8;
        float cs = 0.f;
        #pragma unroll 8
        for (int rr = hf*128; rr < hf*128 + 128; rr++)
            cs += __half2float(E[rr*EST + col]) * alpha[rr];
        csp[t] = cs;
    }
    const half* Vlp = g_VT[0] + (size_t)bh*64*Wn;
    const half* Vrp = g_VT[1] + (size_t)bh*64*Wn;
    for (int lin = t; lin < 2048; lin += 512) {
        int row = lin >> 5, seg = lin & 31;
        *(uint4*)&VTr[row*EST + seg*8] = *(const uint4*)(Vrp + row*Wn + seg*8);
        uint4 v = *(const uint4*)(Vlp + row*Wn + seg*8);
        half2* hp = (half2*)&v;
        #pragma unroll
        for (int i = 0; i < 4; i++) {
            float2 f = __half22float2(hp[i]);
            f.x *= alpha[seg*8 + 2*i];
            f.y *= alpha[seg*8 + 2*i + 1];
            hp[i] = __floats2half2_rn(f.x, f.y);
        }
        *(uint4*)&VTl[row*EST + seg*8] = v;
    }
    __syncthreads();
    if (t < 256) colsum[t] = csp[t] + csp[256 + t];
    __syncthreads();

    // GEMM1: warp -> 16 rows x 32 cols per pass
    for (int pass = 0; pass < 2; pass++) {
        int wbase = (pass*8 + wlow)*16;
        int ccol = whalf*32;
        float acc[4][4];
        #pragma unroll
        for (int i = 0; i < 4; i++) { acc[i][0]=acc[i][1]=acc[i][2]=acc[i][3]=0.f; }
        #pragma unroll 4
        for (int k = 0; k < 16; k++) {
            uint32_t af[4];
            LDSM4(af, Eu + (uint32_t)(((wbase + a_r)*EST + k*16 + a_kh*8)*2));
            #pragma unroll
            for (int g2 = 0; g2 < 2; g2++) {
                uint32_t bf[4];
                LDSM4(bf, VTru + (uint32_t)(((ccol + g2*16 + b_n)*EST + k*16 + b_kh*8)*2));
                MMA_F16(acc[2*g2],   af, bf[0], bf[1]);
                MMA_F16(acc[2*g2+1], af, bf[2], bf[3]);
            }
        }
        int w0r = wbase + r;
        float inv0 = __frcp_rn(rowsum[w0r]), inv1 = __frcp_rn(rowsum[w0r+8]);
        #pragma unroll
        for (int tile = 0; tile < 4; tile++) {
            int c = ccol + tile*8 + c2l;
            float bc0 = __ldg(&beta[c]), bc1 = __ldg(&beta[c+1]);
            size_t i00 = ((size_t)(b*64 + c)*Hn + h)*Wn + w0r;
            out_l[i00]      = x_l[i00]      + bc0*acc[tile][0]*inv0;
            out_l[i00+HW]   = x_l[i00+HW]   + bc1*acc[tile][1]*inv0;
            out_l[i00+8]    = x_l[i00+8]    + bc0*acc[tile][2]*inv1;
            out_l[i00+HW+8] = x_l[i00+HW+8] + bc1*acc[tile][3]*inv1;
        }
    }
    // GEMM2: E^T -> out_r
    for (int pass = 0; pass < 2; pass++) {
        int vbase = (pass*8 + wlow)*16;
        int ccol = whalf*32;
        float acc[4][4];
        #pragma unroll
        for (int i = 0; i < 4; i++) { acc[i][0]=acc[i][1]=acc[i][2]=acc[i][3]=0.f; }
        #pragma unroll 4
        for (int k = 0; k < 16; k++) {
            uint32_t af[4];
            LDSM4T(af, Eu + (uint32_t)(((k*16 + e_r)*EST + vbase + e_kh*8)*2));
            #pragma unroll
            for (int g2 = 0; g2 < 2; g2++) {
                uint32_t bf[4];
                LDSM4(bf, VTlu + (uint32_t)(((ccol + g2*16 + b_n)*EST + k*16 + b_kh*8)*2));
                MMA_F16(acc[2*g2],   af, bf[0], bf[1]);
                MMA_F16(acc[2*g2+1], af, bf[2], bf[3]);
            }
        }
        int v0r = vbase + r;
        float inv0 = __frcp_rn(colsum[v0r]), inv1 = __frcp_rn(colsum[v0r+8]);
        #pragma unroll
        for (int tile = 0; tile < 4; tile++) {
            int c = ccol + tile*8 + c2l;
            float gc0 = __ldg(&gamma[c]), gc1 = __ldg(&gamma[c+1]);
            size_t i00 = ((size_t)(b*64 + c)*Hn + h)*Wn + v0r;
            out_r[i00]      = x_r[i00]      + gc0*acc[tile][0]*inv0;
            out_r[i00+HW]   = x_r[i00+HW]   + gc1*acc[tile][1]*inv0;
            out_r[i00+8]    = x_r[i00+8]    + gc0*acc[tile][2]*inv1;
            out_r[i00+HW+8] = x_r[i00+HW+8] + gc1*acc[tile][3]*inv1;
        }
    }
}

// ---------------- launch ----------------------------------------------------
extern "C" void kernel_launch(void* const* d_in, const int* in_sizes, int n_in,
                              void* d_out, int out_size) {
    const float* x_l   = (const float*)d_in[0];
    const float* x_r   = (const float*)d_in[1];
    const float* lnl_g = (const float*)d_in[2];
    const float* lnl_b = (const float*)d_in[3];
    const float* lnr_g = (const float*)d_in[4];
    const float* lnr_b = (const float*)d_in[5];
    const float* l_dw  = (const float*)d_in[6];
    const float* l_db  = (const float*)d_in[7];
    const float* l_c1w = (const float*)d_in[8];
    const float* l_c1b = (const float*)d_in[9];
    const float* l_pw  = (const float*)d_in[10];
    const float* r_dw  = (const float*)d_in[11];
    const float* r_db  = (const float*)d_in[12];
    const float* r_c1w = (const float*)d_in[13];
    const float* r_c1b = (const float*)d_in[14];
    const float* r_pw  = (const float*)d_in[15];
    const float* l2w   = (const float*)d_in[16];
    const float* l2b   = (const float*)d_in[17];
    const float* r2w   = (const float*)d_in[18];
    const float* r2b   = (const float*)d_in[19];
    const float* beta  = (const float*)d_in[20];
    const float* gamma = (const float*)d_in[21];
    float* out_l = (float*)d_out;
    float* out_r = out_l + (size_t)NELEM;

    cudaFuncSetAttribute(attn_kernel, cudaFuncAttributeMaxDynamicSharedMemorySize, ASMEM);
    cudaFuncSetAttribute(conv_mma_kernel, cudaFuncAttributeMaxDynamicSharedMemorySize, SMEM_CONV);

    dim3 tgrid(Wn/64, Hn, 2*Bn + 1);
    lnv_kernel<<<tgrid, 256>>>(x_l, x_r, lnl_g, lnl_b, lnr_g, lnr_b,
                               l2w, l2b, r2w, r2b, l_dw, r_dw);        // 1

    dim3 cgrid(Hn, 2*Bn*Mn);
    conv_mma_kernel<<<cgrid, 128, SMEM_CONV>>>(l_db, r_db);            // 2

    dim3 sgrid(Bn, 2);
    sw_kernel<<<sgrid, 256>>>(l_c1w, l_c1b, l_pw, r_c1w, r_c1b, r_pw); // 3

    attn_kernel<<<Bn*Hn, 512, ASMEM>>>(x_l, x_r, beta, gamma, out_l, out_r); // 4 <- ncu
}